// round 1
// baseline (speedup 1.0000x reference)
#include <cuda_runtime.h>

// Problem constants (from reference): B=4096 rows, N=16384 cols, M=100 bins.
#define NROWS   4096
#define NCOL    16384
#define NT      128            // threads per CTA (one CTA per row)
#define BINS    101            // searchsorted index range 0..100 (100 never hit)

// Shared memory layout (in floats)
#define HWORDS   (BINS * NT)        // 12928 : per-thread histograms hist[bin][NT]
#define TOT_OFF  (HWORDS)           // 12928 : tot[104] (101 used, padded)
#define WSUM_OFF (TOT_OFF + 104)    // 13032 : warp scan sums [4]
#define WSA_OFF  (WSUM_OFF + 4)     // 13036 : warp reduce sums A [4]
#define WSB_OFF  (WSA_OFF + 4)      // 13040 : warp reduce sums B [4]
#define ENDS_OFF (WSB_OFF + 4)      // 13044 : endpoint stash [4]
#define SMEM_WORDS (ENDS_OFF + 4)   // 13048
#define SMEM_BYTES (SMEM_WORDS * 4) // 52192 bytes -> needs opt-in dynamic smem

// Output layout: roc[4096*100] | deriv[4096*100] | trapz_roc[4096] | trapz_deriv[4096]
#define OFF_DERIV  (NROWS * 100)        // 409600
#define OFF_T1     (2 * NROWS * 100)    // 819200
#define OFF_T2     (OFF_T1 + NROWS)     // 823296

__device__ __forceinline__ void acc_one(float x, float* __restrict__ hTid)
{
    // j0 = rint(99*x) via magic-number trick (exact integer in low mantissa bits)
    const float MAGIC = 12582912.0f;          // 2^23 + 2^22
    const float STEP  = 1.0f / 99.0f;         // fl32(1/99), == reference linspace step
    float fr  = __fmaf_rn(x, 99.0f, MAGIC);
    int   j   = __float_as_int(fr) & 0xFFFF;  // j0 in [0,99]
    float j0f = __fadd_rn(fr, -MAGIC);        // exact (Sterbenz)
    float tj  = __fmul_rn(j0f, STEP);         // == reference t[j0], bit-exact
    if (x > tj) j++;                          // searchsorted 'left' fixup
    // hist[j][tid] += x  (conflict-free: bank = tid%32 always)
    hTid[j << 7] += x;                        // j * NT, NT=128
}

__global__ void __launch_bounds__(NT, 4)
roc_kernel(const float* __restrict__ X, const float* __restrict__ Y,
           float* __restrict__ out)
{
    extern __shared__ float sm[];
    float* hist = sm;
    float* tot  = sm + TOT_OFF;

    const int tid = threadIdx.x;
    const int row = blockIdx.x;
    const int l   = tid & 31;
    const int q   = tid >> 5;

    // ---- zero all shared memory ----
    {
        float4  z4 = make_float4(0.f, 0.f, 0.f, 0.f);
        float4* z  = (float4*)sm;
        #pragma unroll 4
        for (int i = tid; i < SMEM_WORDS / 4; i += NT) z[i] = z4;
    }
    __syncthreads();

    // ---- main loop: 128 elements per thread, vectorized loads ----
    {
        const float4* xr   = (const float4*)(X + (size_t)row * NCOL);
        float*        hTid = hist + tid;
        #pragma unroll 4
        for (int i = 0; i < NCOL / (4 * NT); ++i) {   // 32 iterations
            float4 v = xr[i * NT + tid];
            acc_one(v.x, hTid);
            acc_one(v.y, hTid);
            acc_one(v.z, hTid);
            acc_one(v.w, hTid);
        }
    }
    __syncthreads();

    // ---- Stage A: reduce 128 private copies -> tot[j] ----
    // thread (q,l) handles bins {l, l+32, l+64, l+96} over copy-columns [q*32, q*32+32)
    // diagonal float4 access keeps the LDS.128 at its 4-phase structural floor.
    #pragma unroll
    for (int jj = 0; jj < 4; ++jj) {
        int j = jj * 32 + l;
        if (j < BINS) {
            const float4* rp = (const float4*)(hist + j * NT + q * 32);
            float s0 = 0.f, s1 = 0.f, s2 = 0.f, s3 = 0.f;
            #pragma unroll
            for (int k = 0; k < 8; ++k) {
                float4 v = rp[(k + l) & 7];
                s0 += v.x; s1 += v.y; s2 += v.z; s3 += v.w;
            }
            atomicAdd(&tot[j], (s0 + s1) + (s2 + s3));  // distinct banks per lane
        }
    }
    __syncthreads();

    // ---- Stage B: suffix sums, deriv, trapz, divide by y, write out ----
    // full[k] = hist_total[k+1] for k<99 ; full[99] = tail = tot[100] (==0)
    float fullk = (tid < 100) ? tot[tid + 1] : 0.0f;

    // inclusive prefix scan over the 128 threads (only first 100 nonzero)
    float p = fullk;
    #pragma unroll
    for (int d = 1; d < 32; d <<= 1) {
        float n = __shfl_up_sync(0xFFFFFFFFu, p, d);
        if (l >= d) p += n;
    }
    if (l == 31) sm[WSUM_OFF + q] = p;
    __syncthreads();
    float w0 = sm[WSUM_OFF + 0], w1 = sm[WSUM_OFF + 1];
    float w2 = sm[WSUM_OFF + 2], w3 = sm[WSUM_OFF + 3];
    float total = (w0 + w1) + (w2 + w3);
    float off   = (q > 0 ? w0 : 0.f) + (q > 1 ? w1 : 0.f) + (q > 2 ? w2 : 0.f);
    p += off;                                   // inclusive prefix
    float suffix = total - p + fullk;           // suffix sum over full[]

    float yv    = Y[row];
    float roc   = suffix / yv;
    float dval  = (tid < 99) ? fullk : 0.5f * (tot[99] + tot[98]);
    float deriv = dval / yv;

    if (tid < 100) {
        out[(size_t)row * 100 + tid]             = roc;
        out[OFF_DERIV + (size_t)row * 100 + tid] = deriv;
    }

    // trapz(f) = sum(f) - 0.5*(f[0] + f[99])
    float a = (tid < 100) ? roc : 0.f;
    float b = (tid < 100) ? deriv : 0.f;
    #pragma unroll
    for (int d = 16; d; d >>= 1) {
        a += __shfl_down_sync(0xFFFFFFFFu, a, d);
        b += __shfl_down_sync(0xFFFFFFFFu, b, d);
    }
    if (l == 0) { sm[WSA_OFF + q] = a; sm[WSB_OFF + q] = b; }
    if (tid == 0)  { sm[ENDS_OFF + 0] = roc; sm[ENDS_OFF + 2] = deriv; }
    if (tid == 99) { sm[ENDS_OFF + 1] = roc; sm[ENDS_OFF + 3] = deriv; }
    __syncthreads();

    if (tid == 0) {
        float sA = (sm[WSA_OFF+0] + sm[WSA_OFF+1]) + (sm[WSA_OFF+2] + sm[WSA_OFF+3]);
        float sB = (sm[WSB_OFF+0] + sm[WSB_OFF+1]) + (sm[WSB_OFF+2] + sm[WSB_OFF+3]);
        out[OFF_T1 + row] = sA - 0.5f * (sm[ENDS_OFF+0] + sm[ENDS_OFF+1]);
        out[OFF_T2 + row] = sB - 0.5f * (sm[ENDS_OFF+2] + sm[ENDS_OFF+3]);
    }
}

extern "C" void kernel_launch(void* const* d_in, const int* in_sizes, int n_in,
                              void* d_out, int out_size)
{
    // Identify inputs by size (x: 4096*16384, y: 4096) for robustness.
    const float* X = (const float*)d_in[0];
    const float* Y = (const float*)d_in[1];
    if (n_in >= 2 && in_sizes[0] == NROWS) {  // y came first
        Y = (const float*)d_in[0];
        X = (const float*)d_in[1];
    }
    float* out = (float*)d_out;

    cudaFuncSetAttribute(roc_kernel, cudaFuncAttributeMaxDynamicSharedMemorySize,
                         SMEM_BYTES);
    roc_kernel<<<NROWS, NT, SMEM_BYTES>>>(X, Y, out);
}

// round 3
// speedup vs baseline: 1.2805x; 1.2805x over previous
#include <cuda_runtime.h>

// Problem constants: B=4096 rows, N=16384 cols, M=100 bins.
#define NROWS   4096
#define NCOL    16384
#define NT      128            // threads per CTA (one CTA per row)

// Histogram rows: 0..99 data, 100 = tail (stays 0), 101 = dummy sink, 102-103 pad
#define HROWS   104
#define DUMMY   101

// Shared memory layout (in floats)
#define HWORDS   (HROWS * NT)       // 13312 : per-thread histograms hist[bin][NT]
#define TOT_OFF  (HWORDS)           // tot[104] (101 used, padded)
#define WSUM_OFF (TOT_OFF + 104)
#define WSA_OFF  (WSUM_OFF + 4)
#define WSB_OFF  (WSA_OFF + 4)
#define ENDS_OFF (WSB_OFF + 4)
#define SMEM_WORDS (ENDS_OFF + 4)
#define SMEM_BYTES (SMEM_WORDS * 4) // 53792 bytes (needs opt-in dynamic smem)

// Output layout: roc[4096*100] | deriv[4096*100] | trapz_roc[4096] | trapz_deriv[4096]
#define OFF_DERIV  (NROWS * 100)
#define OFF_T1     (2 * NROWS * 100)
#define OFF_T2     (OFF_T1 + NROWS)

__device__ __forceinline__ int bin_of(float x)
{
    // j0 = rint(99*x) via magic-number trick; exact searchsorted-left fixup
    const float MAGIC = 12582912.0f;          // 2^23 + 2^22
    const float STEP  = 1.0f / 99.0f;         // fl32(1/99) == reference linspace step
    float fr  = __fmaf_rn(x, 99.0f, MAGIC);
    int   j   = __float_as_int(fr) & 0xFFFF;  // j0 in [0,99]
    float j0f = __fadd_rn(fr, -MAGIC);        // exact (Sterbenz)
    float tj  = __fmul_rn(j0f, STEP);         // == reference t[j0], bit-exact
    return j + (x > tj ? 1 : 0);
}

// Pairwise accumulate: both LDS issue before either STS (alias-safe because
// duplicate bins are folded into one update and the other redirected to DUMMY).
__device__ __forceinline__ void acc_pair(float x1, float x2, float* __restrict__ hTid)
{
    int j1 = bin_of(x1);
    int j2 = bin_of(x2);
    bool eq  = (j1 == j2);
    float y2 = eq ? __fadd_rn(x1, x2) : x2;   // fold x1 into x2's update if same bin
    int  j1d = eq ? DUMMY : j1;               // redirect j1's update to sink
    float* p1 = hTid + (j1d << 7);            // * NT
    float* p2 = hTid + (j2  << 7);
    float a = *p1;                            // LDS  ┐ overlapped
    float b = *p2;                            // LDS  ┘
    *p1 = a + x1;                             // STS
    *p2 = b + y2;                             // STS
}

__device__ __forceinline__ void acc16(const float4& v0, const float4& v1,
                                      const float4& v2, const float4& v3,
                                      float* __restrict__ hTid)
{
    acc_pair(v0.x, v0.y, hTid); acc_pair(v0.z, v0.w, hTid);
    acc_pair(v1.x, v1.y, hTid); acc_pair(v1.z, v1.w, hTid);
    acc_pair(v2.x, v2.y, hTid); acc_pair(v2.z, v2.w, hTid);
    acc_pair(v3.x, v3.y, hTid); acc_pair(v3.z, v3.w, hTid);
}

__global__ void __launch_bounds__(NT, 4)
roc_kernel(const float* __restrict__ X, const float* __restrict__ Y,
           float* __restrict__ out)
{
    extern __shared__ float sm[];
    float* hist = sm;
    float* tot  = sm + TOT_OFF;

    const int tid = threadIdx.x;
    const int row = blockIdx.x;
    const int l   = tid & 31;
    const int q   = tid >> 5;

    // ---- zero all shared memory ----
    {
        float4  z4 = make_float4(0.f, 0.f, 0.f, 0.f);
        float4* z  = (float4*)sm;
        #pragma unroll 4
        for (int i = tid; i < SMEM_WORDS / 4; i += NT) z[i] = z4;
    }
    __syncthreads();

    // ---- main loop: 128 elements/thread, software-pipelined loads ----
    // Prefetch distance = 4 float4 (16 elems): 2KB outstanding per warp.
    {
        const float4* xr   = (const float4*)(X + (size_t)row * NCOL) + tid;
        float*        hTid = hist + tid;

        float4 c0 = xr[0 * NT], c1 = xr[1 * NT], c2 = xr[2 * NT], c3 = xr[3 * NT];
        #pragma unroll 1
        for (int i = 0; i < 7; ++i) {
            const float4* pn = xr + (4 * i + 4) * NT;
            float4 n0 = pn[0 * NT], n1 = pn[1 * NT], n2 = pn[2 * NT], n3 = pn[3 * NT];
            acc16(c0, c1, c2, c3, hTid);
            c0 = n0; c1 = n1; c2 = n2; c3 = n3;
        }
        acc16(c0, c1, c2, c3, hTid);
    }
    __syncthreads();

    // ---- Stage A: reduce 128 private copies -> tot[j] (bins 0..100 only) ----
    #pragma unroll
    for (int jj = 0; jj < 4; ++jj) {
        int j = jj * 32 + l;
        if (j < 101) {
            const float4* rp = (const float4*)(hist + j * NT + q * 32);
            float s0 = 0.f, s1 = 0.f, s2 = 0.f, s3 = 0.f;
            #pragma unroll
            for (int k = 0; k < 8; ++k) {
                float4 v = rp[(k + l) & 7];
                s0 += v.x; s1 += v.y; s2 += v.z; s3 += v.w;
            }
            atomicAdd(&tot[j], (s0 + s1) + (s2 + s3));
        }
    }
    __syncthreads();

    // ---- Stage B: suffix sums, deriv, trapz, divide by y, write out ----
    float fullk = (tid < 100) ? tot[tid + 1] : 0.0f;

    float p = fullk;
    #pragma unroll
    for (int d = 1; d < 32; d <<= 1) {
        float n = __shfl_up_sync(0xFFFFFFFFu, p, d);
        if (l >= d) p += n;
    }
    if (l == 31) sm[WSUM_OFF + q] = p;
    __syncthreads();
    float w0 = sm[WSUM_OFF + 0], w1 = sm[WSUM_OFF + 1];
    float w2 = sm[WSUM_OFF + 2], w3 = sm[WSUM_OFF + 3];
    float total = (w0 + w1) + (w2 + w3);
    float off   = (q > 0 ? w0 : 0.f) + (q > 1 ? w1 : 0.f) + (q > 2 ? w2 : 0.f);
    p += off;
    float suffix = total - p + fullk;

    float yv    = Y[row];
    float roc   = suffix / yv;
    float dval  = (tid < 99) ? fullk : 0.5f * (tot[99] + tot[98]);
    float deriv = dval / yv;

    if (tid < 100) {
        out[(size_t)row * 100 + tid]             = roc;
        out[OFF_DERIV + (size_t)row * 100 + tid] = deriv;
    }

    float a = (tid < 100) ? roc : 0.f;
    float b = (tid < 100) ? deriv : 0.f;
    #pragma unroll
    for (int d = 16; d; d >>= 1) {
        a += __shfl_down_sync(0xFFFFFFFFu, a, d);
        b += __shfl_down_sync(0xFFFFFFFFu, b, d);
    }
    if (l == 0) { sm[WSA_OFF + q] = a; sm[WSB_OFF + q] = b; }
    if (tid == 0)  { sm[ENDS_OFF + 0] = roc; sm[ENDS_OFF + 2] = deriv; }
    if (tid == 99) { sm[ENDS_OFF + 1] = roc; sm[ENDS_OFF + 3] = deriv; }
    __syncthreads();

    if (tid == 0) {
        float sA = (sm[WSA_OFF+0] + sm[WSA_OFF+1]) + (sm[WSA_OFF+2] + sm[WSA_OFF+3]);
        float sB = (sm[WSB_OFF+0] + sm[WSB_OFF+1]) + (sm[WSB_OFF+2] + sm[WSB_OFF+3]);
        out[OFF_T1 + row] = sA - 0.5f * (sm[ENDS_OFF+0] + sm[ENDS_OFF+1]);
        out[OFF_T2 + row] = sB - 0.5f * (sm[ENDS_OFF+2] + sm[ENDS_OFF+3]);
    }
}

extern "C" void kernel_launch(void* const* d_in, const int* in_sizes, int n_in,
                              void* d_out, int out_size)
{
    const float* X = (const float*)d_in[0];
    const float* Y = (const float*)d_in[1];
    if (n_in >= 2 && in_sizes[0] == NROWS) {  // y came first
        Y = (const float*)d_in[0];
        X = (const float*)d_in[1];
    }
    float* out = (float*)d_out;

    cudaFuncSetAttribute(roc_kernel, cudaFuncAttributeMaxDynamicSharedMemorySize,
                         SMEM_BYTES);
    roc_kernel<<<NROWS, NT, SMEM_BYTES>>>(X, Y, out);
}

// round 6
// speedup vs baseline: 1.4149x; 1.1049x over previous
#include <cuda_runtime.h>

// Problem constants: B=4096 rows, N=16384 cols, M=100 bins.
#define NROWS   4096
#define NCOL    16384
#define NT      128            // threads per CTA (one CTA per row)

// Histogram rows: 0..99 data, 100 = tail (stays 0), 101 = dummy sink, 102-103 pad
#define HROWS   104
#define DUMMY   101

// Shared memory layout (in floats)
#define HWORDS   (HROWS * NT)       // 13312 : per-thread histograms hist[bin][NT]
#define TOT_OFF  (HWORDS)           // tot[104] (101 used, padded)
#define WSUM_OFF (TOT_OFF + 104)
#define WSA_OFF  (WSUM_OFF + 4)
#define WSB_OFF  (WSA_OFF + 4)
#define ENDS_OFF (WSB_OFF + 4)
#define SMEM_WORDS (ENDS_OFF + 4)
#define SMEM_BYTES (SMEM_WORDS * 4) // 53792 bytes (needs opt-in dynamic smem)

// Output layout: roc[4096*100] | deriv[4096*100] | trapz_roc[4096] | trapz_deriv[4096]
#define OFF_DERIV  (NROWS * 100)
#define OFF_T1     (2 * NROWS * 100)
#define OFF_T2     (OFF_T1 + NROWS)

__device__ __forceinline__ int bin_of(float x)
{
    // j0 = rint(99*x) via magic-number trick; exact searchsorted-left fixup
    const float MAGIC = 12582912.0f;          // 2^23 + 2^22
    const float STEP  = 1.0f / 99.0f;         // fl32(1/99) == reference linspace step
    float fr  = __fmaf_rn(x, 99.0f, MAGIC);
    int   j   = __float_as_int(fr) & 0xFFFF;  // j0 in [0,99]
    float j0f = __fadd_rn(fr, -MAGIC);        // exact (Sterbenz)
    float tj  = __fmul_rn(j0f, STEP);         // == reference t[j0], bit-exact
    return j + (x > tj ? 1 : 0);
}

// Pairwise accumulate: both LDS issue before either STS (alias-safe because
// duplicate bins are folded into one update and the other redirected to DUMMY).
__device__ __forceinline__ void acc_pair(float x1, float x2, float* __restrict__ hTid)
{
    int j1 = bin_of(x1);
    int j2 = bin_of(x2);
    bool eq  = (j1 == j2);
    float y2 = eq ? __fadd_rn(x1, x2) : x2;   // fold x1 into x2's update if same bin
    int  j1d = eq ? DUMMY : j1;               // redirect j1's update to sink
    float* p1 = hTid + (j1d << 7);            // * NT
    float* p2 = hTid + (j2  << 7);
    float a = *p1;                            // LDS  ┐ overlapped
    float b = *p2;                            // LDS  ┘
    *p1 = a + x1;                             // STS
    *p2 = b + y2;                             // STS
}

__device__ __forceinline__ void acc16(const float4& v0, const float4& v1,
                                      const float4& v2, const float4& v3,
                                      float* __restrict__ hTid)
{
    acc_pair(v0.x, v0.y, hTid); acc_pair(v0.z, v0.w, hTid);
    acc_pair(v1.x, v1.y, hTid); acc_pair(v1.z, v1.w, hTid);
    acc_pair(v2.x, v2.y, hTid); acc_pair(v2.z, v2.w, hTid);
    acc_pair(v3.x, v3.y, hTid); acc_pair(v3.z, v3.w, hTid);
}

__global__ void __launch_bounds__(NT, 4)
roc_kernel(const float* __restrict__ X, const float* __restrict__ Y,
           float* __restrict__ out)
{
    extern __shared__ float sm[];
    float* hist = sm;
    float* tot  = sm + TOT_OFF;

    const int tid = threadIdx.x;
    const int row = blockIdx.x;
    const int l   = tid & 31;
    const int q   = tid >> 5;

    const float4* xr = (const float4*)(X + (size_t)row * NCOL) + tid;

    // ---- pipeline fill: issue first 8 LDG.128 BEFORE smem zeroing so their
    // DRAM latency hides behind the zeroing stores instead of being exposed.
    float4 a0 = xr[0 * NT], a1 = xr[1 * NT], a2 = xr[2 * NT], a3 = xr[3 * NT];
    float4 b0 = xr[4 * NT], b1 = xr[5 * NT], b2 = xr[6 * NT], b3 = xr[7 * NT];

    // ---- zero all shared memory ----
    {
        float4  z4 = make_float4(0.f, 0.f, 0.f, 0.f);
        float4* z  = (float4*)sm;
        #pragma unroll 4
        for (int i = tid; i < SMEM_WORDS / 4; i += NT) z[i] = z4;
    }
    __syncthreads();

    // ---- main loop: 128 elems/thread, DOUBLE-buffered software pipeline ----
    // Prefetch distance = 2 iterations (8 float4 = 4KB outstanding per warp),
    // matching ~600cyc DRAM latency against ~280cyc of work per iteration.
    {
        float* hTid = hist + tid;

        #pragma unroll 1
        for (int i = 0; i < 6; i += 2) {
            const float4* pA = xr + (4 * i +  8) * NT;   // iter i+2
            float4 n0 = pA[0 * NT], n1 = pA[1 * NT], n2 = pA[2 * NT], n3 = pA[3 * NT];
            acc16(a0, a1, a2, a3, hTid);                  // iter i
            a0 = n0; a1 = n1; a2 = n2; a3 = n3;

            const float4* pB = xr + (4 * i + 12) * NT;   // iter i+3
            float4 m0 = pB[0 * NT], m1 = pB[1 * NT], m2 = pB[2 * NT], m3 = pB[3 * NT];
            acc16(b0, b1, b2, b3, hTid);                  // iter i+1
            b0 = m0; b1 = m1; b2 = m2; b3 = m3;
        }
        acc16(a0, a1, a2, a3, hTid);                      // iter 6
        acc16(b0, b1, b2, b3, hTid);                      // iter 7
    }
    __syncthreads();

    // ---- Stage A: reduce 128 private copies -> tot[j] (bins 0..100 only) ----
    #pragma unroll
    for (int jj = 0; jj < 4; ++jj) {
        int j = jj * 32 + l;
        if (j < 101) {
            const float4* rp = (const float4*)(hist + j * NT + q * 32);
            float s0 = 0.f, s1 = 0.f, s2 = 0.f, s3 = 0.f;
            #pragma unroll
            for (int k = 0; k < 8; ++k) {
                float4 v = rp[(k + l) & 7];
                s0 += v.x; s1 += v.y; s2 += v.z; s3 += v.w;
            }
            atomicAdd(&tot[j], (s0 + s1) + (s2 + s3));
        }
    }
    __syncthreads();

    // ---- Stage B: suffix sums, deriv, trapz, divide by y, write out ----
    float fullk = (tid < 100) ? tot[tid + 1] : 0.0f;

    float p = fullk;
    #pragma unroll
    for (int d = 1; d < 32; d <<= 1) {
        float n = __shfl_up_sync(0xFFFFFFFFu, p, d);
        if (l >= d) p += n;
    }
    if (l == 31) sm[WSUM_OFF + q] = p;
    __syncthreads();
    float w0 = sm[WSUM_OFF + 0], w1 = sm[WSUM_OFF + 1];
    float w2 = sm[WSUM_OFF + 2], w3 = sm[WSUM_OFF + 3];
    float total = (w0 + w1) + (w2 + w3);
    float off   = (q > 0 ? w0 : 0.f) + (q > 1 ? w1 : 0.f) + (q > 2 ? w2 : 0.f);
    p += off;
    float suffix = total - p + fullk;

    float yv    = Y[row];
    float roc   = suffix / yv;
    float dval  = (tid < 99) ? fullk : 0.5f * (tot[99] + tot[98]);
    float deriv = dval / yv;

    if (tid < 100) {
        out[(size_t)row * 100 + tid]             = roc;
        out[OFF_DERIV + (size_t)row * 100 + tid] = deriv;
    }

    float a = (tid < 100) ? roc : 0.f;
    float b = (tid < 100) ? deriv : 0.f;
    #pragma unroll
    for (int d = 16; d; d >>= 1) {
        a += __shfl_down_sync(0xFFFFFFFFu, a, d);
        b += __shfl_down_sync(0xFFFFFFFFu, b, d);
    }
    if (l == 0) { sm[WSA_OFF + q] = a; sm[WSB_OFF + q] = b; }
    if (tid == 0)  { sm[ENDS_OFF + 0] = roc; sm[ENDS_OFF + 2] = deriv; }
    if (tid == 99) { sm[ENDS_OFF + 1] = roc; sm[ENDS_OFF + 3] = deriv; }
    __syncthreads();

    if (tid == 0) {
        float sA = (sm[WSA_OFF+0] + sm[WSA_OFF+1]) + (sm[WSA_OFF+2] + sm[WSA_OFF+3]);
        float sB = (sm[WSB_OFF+0] + sm[WSB_OFF+1]) + (sm[WSB_OFF+2] + sm[WSB_OFF+3]);
        out[OFF_T1 + row] = sA - 0.5f * (sm[ENDS_OFF+0] + sm[ENDS_OFF+1]);
        out[OFF_T2 + row] = sB - 0.5f * (sm[ENDS_OFF+2] + sm[ENDS_OFF+3]);
    }
}

extern "C" void kernel_launch(void* const* d_in, const int* in_sizes, int n_in,
                              void* d_out, int out_size)
{
    const float* X = (const float*)d_in[0];
    const float* Y = (const float*)d_in[1];
    if (n_in >= 2 && in_sizes[0] == NROWS) {  // y came first
        Y = (const float*)d_in[0];
        X = (const float*)d_in[1];
    }
    float* out = (float*)d_out;

    cudaFuncSetAttribute(roc_kernel, cudaFuncAttributeMaxDynamicSharedMemorySize,
                         SMEM_BYTES);
    roc_kernel<<<NROWS, NT, SMEM_BYTES>>>(X, Y, out);
}